// round 10
// baseline (speedup 1.0000x reference)
#include <cuda_runtime.h>

// Problem constants (fixed by the reference)
#define BB   4
#define CC   32
#define HH   64
#define WW   64
#define KK   64
#define HWV  (HH*WW)      // 4096
#define BCV  (BB*CC)      // 128
#define CAP  1024         // max support pixels per RF (analysis: <= ~932 padded)
#define NU   1024         // output units per image (32*32)

// ---------------- static device scratch (no allocation allowed) -------------
__device__ int   g_cnt [KK];          // PADDED (x4) support size per k
__device__ float g_base[KK];          // 1.0f - (#pad entries) per k
__device__ int   g_pk  [KK*CAP];      // per-k list, packed {rf20 | pixel12}
__device__ int   g_uc  [NU];          // entries per unit (padded to x4)
__device__ int   g_pxt [KK*NU*4];     // unit-major lists: int4 at (j*NU+unit)
                                      // = 4 pixels' j-th entries {rf25|k7}
__device__ float g_inv [BCV*KK];      // 1/(base + sum) per (bc,k)

__device__ __forceinline__ float ex2_fast(float y) {
    float r;
    asm("ex2.approx.f32 %0, %1;" : "=f"(r) : "f"(y));
    return r;
}

// ---------------- PREP (single kernel, 80 blocks) ---------------------------
// blocks 0..63 : per-k compact support list (raster order, padded to x4)
// blocks 64..79: unit-major per-pixel lists (64 units each), k ascending,
//                each pixel's list padded to the unit max with nulls (k=64).
// All orders fixed -> deterministic.
__global__ __launch_bounds__(1024) void prep(const float* __restrict__ rfs) {
    const int tid = threadIdx.x;
    const float LOG2E = 1.4426950408889634f;

    __shared__ int wtot[32];
    __shared__ int woff[32];
    __shared__ int qc[256][4];

    if (blockIdx.x < 64) {
        const int k    = blockIdx.x;
        const int lane = tid & 31;
        const int wid  = tid >> 5;

        const float4 r = ((const float4*)(rfs + k*HWV))[tid];
        const int f0 = (r.x != 0.0f), f1 = (r.y != 0.0f), f2 = (r.z != 0.0f), f3 = (r.w != 0.0f);
        const int cnt = f0 + f1 + f2 + f3;

        int s = cnt;
        #pragma unroll
        for (int o = 1; o < 32; o <<= 1) {
            int t = __shfl_up_sync(0xffffffffu, s, o);
            if (lane >= o) s += t;
        }
        const int excl = s - cnt;
        if (lane == 31) wtot[wid] = s;
        __syncthreads();
        if (wid == 0) {
            int v = wtot[lane], ss = v;
            #pragma unroll
            for (int o = 1; o < 32; o <<= 1) {
                int t = __shfl_up_sync(0xffffffffu, ss, o);
                if (lane >= o) ss += t;
            }
            woff[lane] = ss - v;
            if (lane == 31) {
                const int n  = (ss < CAP) ? ss : CAP;
                const int n4 = (n + 3) & ~3;
                g_cnt[k]  = n4;
                g_base[k] = 1.0f - (float)(n4 - n);
                for (int j = n; j < n4; j++) g_pk[k*CAP + j] = 0;  // pad: exp(0)=1, cancelled by base
            }
        }
        __syncthreads();

        int base = woff[wid] + excl;
        const int p0 = tid * 4;
        int* __restrict__ dst = g_pk + k*CAP;
        #define PACK_A(val, pix) (((__float_as_int((val)*LOG2E) + 0x800) & 0xFFFFF000) | (pix))
        if (f0 && base < CAP) { dst[base] = PACK_A(r.x, p0);     base++; }
        if (f1 && base < CAP) { dst[base] = PACK_A(r.y, p0 + 1); base++; }
        if (f2 && base < CAP) { dst[base] = PACK_A(r.z, p0 + 2); base++; }
        if (f3 && base < CAP) { dst[base] = PACK_A(r.w, p0 + 3); base++; }
        #undef PACK_A
    } else {
        // unit-major lists. tid = pl*4 + q; pl = pixel-in-block (pooled order),
        // q = k-quarter (16 k each). Block covers 64 units (256 pixels).
        const int q  = tid & 3;
        const int pl = tid >> 2;
        const int ug = (blockIdx.x - 64) * 64 + (pl >> 2);   // global unit
        const int wn = pl & 3;                               // pixel within unit
        const int y  = 2*(ug >> 5) + (wn >> 1);
        const int x  = 2*(ug & 31) + (wn & 1);
        const int p  = y*WW + x;

        float rv[16];
        int cq = 0;
        #pragma unroll
        for (int i = 0; i < 16; i++) {
            rv[i] = rfs[(q*16 + i)*HWV + p];
            cq += (rv[i] != 0.0f);
        }
        qc[pl][q] = cq;
        __syncthreads();

        const int c = qc[pl][0] + qc[pl][1] + qc[pl][2] + qc[pl][3];   // pixel total
        int off = 0;
        #pragma unroll
        for (int qq = 0; qq < 4; qq++) if (qq < q) off += qc[pl][qq];

        // unit max over the 4 pixels: lanes of a unit span tid groups of 16
        int cm = c;
        cm = max(cm, __shfl_xor_sync(0xffffffffu, cm, 4));
        cm = max(cm, __shfl_xor_sync(0xffffffffu, cm, 8));
        const int cm4 = (cm + 3) & ~3;

        #pragma unroll
        for (int i = 0; i < 16; i++) {
            if (rv[i] != 0.0f) {
                const int k    = q*16 + i;
                const int bits = ((__float_as_int(rv[i] * LOG2E) + 0x40) & 0xFFFFFF80) | k;
                g_pxt[(off*NU + ug)*4 + wn] = bits;
                off++;
            }
        }
        if (q == 3) {                           // off == c here; pad to cm4
            for (int j = c; j < cm4; j++)
                g_pxt[(j*NU + ug)*4 + wn] = 64; // null: rf=+0, k=64 -> 0
            if (wn == 0) g_uc[ug] = cm4;
        }
    }
}

// ---------------- K_A: denominators, warp-per-(bc,k), no smem/barriers ------
// exp(v - m)/(exp(-m) + sum exp(v - m)) == exp(v)/(1 + sum exp(v)).
__global__ __launch_bounds__(256) void k_denom(const float* __restrict__ u) {
    const int bc   = blockIdx.x >> 3;
    const int kc   = blockIdx.x & 7;
    const int lane = threadIdx.x & 31;
    const int k    = kc*8 + (threadIdx.x >> 5);

    const int n4 = g_cnt[k];
    const int* __restrict__ pr = g_pk + k*CAP;
    const float* __restrict__ ub = u + bc*HWV;

    float sum = 0.0f;
    #pragma unroll 4
    for (int j = lane; j < n4; j += 32) {
        const int bits = pr[j];                            // coalesced LDG.32
        sum += ex2_fast(ub[bits & 0xFFF] * __int_as_float(bits & 0xFFFFF000));
    }
    #pragma unroll
    for (int o = 16; o > 0; o >>= 1) sum += __shfl_down_sync(0xffffffffu, sum, o);
    if (lane == 0) g_inv[bc*KK + k] = 1.0f / (g_base[k] + sum);
}

// ---------------- K_B: per-unit numerators + max, direct store --------------
// Thread = one output unit: 4 register accumulators (its 2x2 pixels), one
// coalesced LDG.128 per list entry-row, unrolled x4 (16 entries in flight).
__global__ __launch_bounds__(256) void k_numer(const float* __restrict__ u,
                                               float* __restrict__ out) {
    __shared__ float inv_s[128];     // [64..127] = 0 for null entries

    const int bc  = blockIdx.x >> 2;
    const int seg = blockIdx.x & 3;
    const int tid = threadIdx.x;

    if (tid < 64)        inv_s[tid] = g_inv[bc*KK + tid];
    else if (tid < 128)  inv_s[tid] = 0.0f;
    __syncthreads();

    const int ug = seg*256 + tid;                // global unit
    const int gb = bc*HWV + 2*(ug >> 5)*WW + 2*(ug & 31);
    const float u0 = u[gb], u1 = u[gb + 1], u2 = u[gb + WW], u3 = u[gb + WW + 1];
    const int cn = g_uc[ug];                     // multiple of 4

    const int4* __restrict__ PT = (const int4*)g_pxt;
    float a0 = 0.0f, a1 = 0.0f, a2 = 0.0f, a3 = 0.0f;

    #define RFV(b) __int_as_float((b) & 0xFFFFFF80)
    for (int j = 0; j < cn; j += 4) {
        const int4 b0 = PT[(j + 0)*NU + ug];     // 4 independent LDG.128,
        const int4 b1 = PT[(j + 1)*NU + ug];     // perfectly lane-coalesced
        const int4 b2 = PT[(j + 2)*NU + ug];
        const int4 b3 = PT[(j + 3)*NU + ug];
        a0 += ex2_fast(u0 * RFV(b0.x)) * inv_s[b0.x & 127];
        a1 += ex2_fast(u1 * RFV(b0.y)) * inv_s[b0.y & 127];
        a2 += ex2_fast(u2 * RFV(b0.z)) * inv_s[b0.z & 127];
        a3 += ex2_fast(u3 * RFV(b0.w)) * inv_s[b0.w & 127];
        a0 += ex2_fast(u0 * RFV(b1.x)) * inv_s[b1.x & 127];
        a1 += ex2_fast(u1 * RFV(b1.y)) * inv_s[b1.y & 127];
        a2 += ex2_fast(u2 * RFV(b1.z)) * inv_s[b1.z & 127];
        a3 += ex2_fast(u3 * RFV(b1.w)) * inv_s[b1.w & 127];
        a0 += ex2_fast(u0 * RFV(b2.x)) * inv_s[b2.x & 127];
        a1 += ex2_fast(u1 * RFV(b2.y)) * inv_s[b2.y & 127];
        a2 += ex2_fast(u2 * RFV(b2.z)) * inv_s[b2.z & 127];
        a3 += ex2_fast(u3 * RFV(b2.w)) * inv_s[b2.w & 127];
        a0 += ex2_fast(u0 * RFV(b3.x)) * inv_s[b3.x & 127];
        a1 += ex2_fast(u1 * RFV(b3.y)) * inv_s[b3.y & 127];
        a2 += ex2_fast(u2 * RFV(b3.z)) * inv_s[b3.z & 127];
        a3 += ex2_fast(u3 * RFV(b3.w)) * inv_s[b3.w & 127];
    }
    #undef RFV

    const float best = fmaxf(fmaxf(fmaxf(a0, a1), fmaxf(a2, a3)), 0.0f);
    out[bc*NU + ug] = best;
}

// ---------------- launch -----------------------------------------------------
extern "C" void kernel_launch(void* const* d_in, const int* in_sizes, int n_in,
                              void* d_out, int out_size) {
    const float* u   = (const float*)d_in[0];   // (4,32,64,64)
    const float* rfs = (const float*)d_in[1];   // (64,64,64)
    float* out = (float*)d_out;                 // (4,32,32,32)

    prep   <<<80,    1024>>>(rfs);
    k_denom<<<BCV*8, 256>>>(u);
    k_numer<<<BCV*4, 256>>>(u, out);
}

// round 11
// speedup vs baseline: 1.0949x; 1.0949x over previous
#include <cuda_runtime.h>

// Problem constants (fixed by the reference)
#define BB   4
#define CC   32
#define HH   64
#define WW   64
#define KK   64
#define HWV  (HH*WW)      // 4096
#define BCV  (BB*CC)      // 128
#define CAP  1024         // per-k list capacity (multiple of 128)
#define NU   1024         // output units per image (32*32)

// ---------------- static device scratch (no allocation allowed) -------------
__device__ int   g_cnt [KK];          // per-k list length, PADDED to x128
__device__ float g_base[KK];          // 1.0f - (#pad entries) per k
__device__ int   g_pk  [KK*CAP];      // per-k list, packed {rf20 | pixel12}
__device__ int   g_uc  [NU];          // entries per unit (padded to x4)
__device__ int   g_pxt [KK*NU*4];     // unit-major lists: int4 at (j*NU+unit)
                                      // = 4 pixels' j-th entries {rf25|k7}
__device__ float g_inv [BCV*KK];      // 1/(base + sum) per (bc,k)

__device__ __forceinline__ float ex2_fast(float y) {
    float r;
    asm("ex2.approx.f32 %0, %1;" : "=f"(r) : "f"(y));
    return r;
}

// ---------------- PREP (single kernel, 80 blocks x 256 threads) -------------
// blocks 0..63 : per-k compact support list (raster order, padded to x128
//                with {rf=0,pix=0}: each pad contributes exp(0)=1, exactly
//                cancelled by g_base).
// blocks 64..79: unit-major per-pixel lists, thread-per-pixel, NO barriers.
// All orders fixed -> deterministic.
__global__ __launch_bounds__(256) void prep(const float* __restrict__ rfs) {
    const int tid = threadIdx.x;
    const float LOG2E = 1.4426950408889634f;

    if (blockIdx.x < 64) {
        const int k    = blockIdx.x;
        const int lane = tid & 31;
        const int wid  = tid >> 5;
        __shared__ int wtot[8];
        __shared__ int woff[8];
        __shared__ int sn;

        // 16 pixels per thread, held in registers
        float vals[16];
        int cnt = 0;
        #pragma unroll
        for (int i = 0; i < 4; i++) {
            const float4 r = ((const float4*)(rfs + k*HWV))[tid*4 + i];
            vals[i*4 + 0] = r.x; vals[i*4 + 1] = r.y;
            vals[i*4 + 2] = r.z; vals[i*4 + 3] = r.w;
            cnt += (r.x != 0.0f) + (r.y != 0.0f) + (r.z != 0.0f) + (r.w != 0.0f);
        }

        int s = cnt;                             // warp inclusive scan
        #pragma unroll
        for (int o = 1; o < 32; o <<= 1) {
            int t = __shfl_up_sync(0xffffffffu, s, o);
            if (lane >= o) s += t;
        }
        const int excl = s - cnt;
        if (lane == 31) wtot[wid] = s;
        __syncthreads();
        if (tid < 8) {                           // scan 8 warp totals
            int v = wtot[tid], ss = v;
            #pragma unroll
            for (int o = 1; o < 8; o <<= 1) {
                int t = __shfl_up_sync(0xffu, ss, o);
                if (tid >= o) ss += t;
            }
            woff[tid] = ss - v;
            if (tid == 7) sn = ss;
        }
        __syncthreads();

        int base = woff[wid] + excl;
        const int p0 = tid * 16;
        int* __restrict__ dst = g_pk + k*CAP;
        #pragma unroll
        for (int i = 0; i < 16; i++) {
            if (vals[i] != 0.0f && base < CAP) {
                dst[base] = ((__float_as_int(vals[i]*LOG2E) + 0x800) & 0xFFFFF000) | (p0 + i);
                base++;
            }
        }

        const int n    = (sn < CAP) ? sn : CAP;
        const int n128 = (n + 127) & ~127;       // <= CAP
        for (int j = n + tid; j < n128; j += 256) dst[j] = 0;   // pads
        if (tid == 0) { g_cnt[k] = n128; g_base[k] = 1.0f - (float)(n128 - n); }
    } else {
        // thread-per-pixel (pooled order), 256 pixels = 64 units per block
        const int ug = (blockIdx.x - 64) * 64 + (tid >> 2);
        const int wn = tid & 3;
        const int y  = 2*(ug >> 5) + (wn >> 1);
        const int x  = 2*(ug & 31) + (wn & 1);
        const int p  = y*WW + x;

        int off = 0;
        #pragma unroll 8
        for (int k = 0; k < KK; k++) {
            const float v = rfs[k*HWV + p];
            if (v != 0.0f) {
                const int bits = ((__float_as_int(v*LOG2E) + 0x40) & 0xFFFFFF80) | k;
                g_pxt[(off*NU + ug)*4 + wn] = bits;
                off++;
            }
        }
        // unit max over its 4 lanes (consecutive in-warp), pad to x4
        int cm = off;
        cm = max(cm, __shfl_xor_sync(0xffffffffu, cm, 1));
        cm = max(cm, __shfl_xor_sync(0xffffffffu, cm, 2));
        const int cm4 = (cm + 3) & ~3;
        for (int j = off; j < cm4; j++)
            g_pxt[(j*NU + ug)*4 + wn] = 64;      // null: rf=+0, k=64 -> 0
        if (wn == 0) g_uc[ug] = cm4;
    }
}

// ---------------- K_A: denominators, warp-per-(bc,k), branch-free -----------
// exp(v - m)/(exp(-m) + sum exp(v - m)) == exp(v)/(1 + sum exp(v)).
// n128 is a multiple of 128 -> inner body has NO predicates: 4 independent
// list loads + 4 independent u-gathers in flight every iteration.
__global__ __launch_bounds__(256) void k_denom(const float* __restrict__ u) {
    const int bc   = blockIdx.x >> 3;
    const int kc   = blockIdx.x & 7;
    const int lane = threadIdx.x & 31;
    const int k    = kc*8 + (threadIdx.x >> 5);

    const int n128 = g_cnt[k];
    const int* __restrict__ pr = g_pk + k*CAP;
    const float* __restrict__ ub = u + bc*HWV;

    float s0 = 0.0f, s1 = 0.0f, s2 = 0.0f, s3 = 0.0f;
    for (int j = lane; j < n128; j += 128) {
        const int b0 = pr[j];
        const int b1 = pr[j + 32];
        const int b2 = pr[j + 64];
        const int b3 = pr[j + 96];
        s0 += ex2_fast(ub[b0 & 0xFFF] * __int_as_float(b0 & 0xFFFFF000));
        s1 += ex2_fast(ub[b1 & 0xFFF] * __int_as_float(b1 & 0xFFFFF000));
        s2 += ex2_fast(ub[b2 & 0xFFF] * __int_as_float(b2 & 0xFFFFF000));
        s3 += ex2_fast(ub[b3 & 0xFFF] * __int_as_float(b3 & 0xFFFFF000));
    }
    float sum = (s0 + s1) + (s2 + s3);
    #pragma unroll
    for (int o = 16; o > 0; o >>= 1) sum += __shfl_down_sync(0xffffffffu, sum, o);
    if (lane == 0) g_inv[bc*KK + k] = 1.0f / (g_base[k] + sum);
}

// ---------------- K_B: per-unit numerators + max, direct store --------------
// Thread = one output unit: 4 register accumulators (its 2x2 pixels), one
// coalesced LDG.128 per list entry-row, unrolled x4 (16 entries in flight).
__global__ __launch_bounds__(256) void k_numer(const float* __restrict__ u,
                                               float* __restrict__ out) {
    __shared__ float inv_s[128];     // [64..127] = 0 for null entries

    const int bc  = blockIdx.x >> 2;
    const int seg = blockIdx.x & 3;
    const int tid = threadIdx.x;

    if (tid < 64)        inv_s[tid] = g_inv[bc*KK + tid];
    else if (tid < 128)  inv_s[tid] = 0.0f;
    __syncthreads();

    const int ug = seg*256 + tid;                // global unit
    const int gb = bc*HWV + 2*(ug >> 5)*WW + 2*(ug & 31);
    const float u0 = u[gb], u1 = u[gb + 1], u2 = u[gb + WW], u3 = u[gb + WW + 1];
    const int cn = g_uc[ug];                     // multiple of 4

    const int4* __restrict__ PT = (const int4*)g_pxt;
    float a0 = 0.0f, a1 = 0.0f, a2 = 0.0f, a3 = 0.0f;

    #define RFV(b) __int_as_float((b) & 0xFFFFFF80)
    for (int j = 0; j < cn; j += 4) {
        const int4 b0 = PT[(j + 0)*NU + ug];     // 4 independent LDG.128,
        const int4 b1 = PT[(j + 1)*NU + ug];     // perfectly lane-coalesced
        const int4 b2 = PT[(j + 2)*NU + ug];
        const int4 b3 = PT[(j + 3)*NU + ug];
        a0 += ex2_fast(u0 * RFV(b0.x)) * inv_s[b0.x & 127];
        a1 += ex2_fast(u1 * RFV(b0.y)) * inv_s[b0.y & 127];
        a2 += ex2_fast(u2 * RFV(b0.z)) * inv_s[b0.z & 127];
        a3 += ex2_fast(u3 * RFV(b0.w)) * inv_s[b0.w & 127];
        a0 += ex2_fast(u0 * RFV(b1.x)) * inv_s[b1.x & 127];
        a1 += ex2_fast(u1 * RFV(b1.y)) * inv_s[b1.y & 127];
        a2 += ex2_fast(u2 * RFV(b1.z)) * inv_s[b1.z & 127];
        a3 += ex2_fast(u3 * RFV(b1.w)) * inv_s[b1.w & 127];
        a0 += ex2_fast(u0 * RFV(b2.x)) * inv_s[b2.x & 127];
        a1 += ex2_fast(u1 * RFV(b2.y)) * inv_s[b2.y & 127];
        a2 += ex2_fast(u2 * RFV(b2.z)) * inv_s[b2.z & 127];
        a3 += ex2_fast(u3 * RFV(b2.w)) * inv_s[b2.w & 127];
        a0 += ex2_fast(u0 * RFV(b3.x)) * inv_s[b3.x & 127];
        a1 += ex2_fast(u1 * RFV(b3.y)) * inv_s[b3.y & 127];
        a2 += ex2_fast(u2 * RFV(b3.z)) * inv_s[b3.z & 127];
        a3 += ex2_fast(u3 * RFV(b3.w)) * inv_s[b3.w & 127];
    }
    #undef RFV

    const float best = fmaxf(fmaxf(fmaxf(a0, a1), fmaxf(a2, a3)), 0.0f);
    out[bc*NU + ug] = best;
}

// ---------------- launch -----------------------------------------------------
extern "C" void kernel_launch(void* const* d_in, const int* in_sizes, int n_in,
                              void* d_out, int out_size) {
    const float* u   = (const float*)d_in[0];   // (4,32,64,64)
    const float* rfs = (const float*)d_in[1];   // (64,64,64)
    float* out = (float*)d_out;                 // (4,32,32,32)

    prep   <<<80,    256>>>(rfs);
    k_denom<<<BCV*8, 256>>>(u);
    k_numer<<<BCV*4, 256>>>(u, out);
}

// round 12
// speedup vs baseline: 1.0965x; 1.0015x over previous
#include <cuda_runtime.h>

// Problem constants (fixed by the reference)
#define BB   4
#define CC   32
#define HH   64
#define WW   64
#define KK   64
#define HWV  (HH*WW)      // 4096
#define BCV  (BB*CC)      // 128
#define CAP  1024         // per-k list capacity (multiple of 128)
#define NU   1024         // output units per image (32*32)

// ---------------- static device scratch (no allocation allowed) -------------
__device__ int   g_cnt [KK];          // per-k list length, PADDED to x128
__device__ float g_base[KK];          // 1.0f - (#pad entries) per k
__device__ int   g_pk  [KK*CAP];      // per-k list, packed {rf20 | pixel12}
__device__ int   g_uc  [NU];          // entries per unit (padded to x4)
__device__ int   g_pxt [KK*NU*4];     // unit-major lists: int4 at (j*NU+unit)
                                      // = 4 pixels' j-th entries {rf25|k7}
__device__ float g_inv [BCV*KK];      // 1/(base + sum) per (bc,k)

__device__ __forceinline__ float ex2_fast(float y) {
    float r;
    asm("ex2.approx.f32 %0, %1;" : "=f"(r) : "f"(y));
    return r;
}

// ---------------- P1: per-k compact support lists (64 blocks) ---------------
// Raster order, padded to x128 with {rf=0,pix=0}: each pad contributes
// exp(0)=1, exactly cancelled by g_base. Deterministic.
__global__ __launch_bounds__(256) void prep_k(const float* __restrict__ rfs) {
    const int k    = blockIdx.x;
    const int tid  = threadIdx.x;
    const int lane = tid & 31;
    const int wid  = tid >> 5;
    __shared__ int wtot[8];
    __shared__ int woff[8];
    __shared__ int sn;

    const float LOG2E = 1.4426950408889634f;

    // 16 pixels per thread, held in registers (MLP 4x float4)
    float vals[16];
    int cnt = 0;
    #pragma unroll
    for (int i = 0; i < 4; i++) {
        const float4 r = ((const float4*)(rfs + k*HWV))[tid*4 + i];
        vals[i*4 + 0] = r.x; vals[i*4 + 1] = r.y;
        vals[i*4 + 2] = r.z; vals[i*4 + 3] = r.w;
        cnt += (r.x != 0.0f) + (r.y != 0.0f) + (r.z != 0.0f) + (r.w != 0.0f);
    }

    int s = cnt;                             // warp inclusive scan
    #pragma unroll
    for (int o = 1; o < 32; o <<= 1) {
        int t = __shfl_up_sync(0xffffffffu, s, o);
        if (lane >= o) s += t;
    }
    const int excl = s - cnt;
    if (lane == 31) wtot[wid] = s;
    __syncthreads();
    if (tid < 8) {                           // scan 8 warp totals
        int v = wtot[tid], ss = v;
        #pragma unroll
        for (int o = 1; o < 8; o <<= 1) {
            int t = __shfl_up_sync(0xffu, ss, o);
            if (tid >= o) ss += t;
        }
        woff[tid] = ss - v;
        if (tid == 7) sn = ss;
    }
    __syncthreads();

    int base = woff[wid] + excl;
    const int p0 = tid * 16;
    int* __restrict__ dst = g_pk + k*CAP;
    #pragma unroll
    for (int i = 0; i < 16; i++) {
        if (vals[i] != 0.0f && base < CAP) {
            dst[base] = ((__float_as_int(vals[i]*LOG2E) + 0x800) & 0xFFFFF000) | (p0 + i);
            base++;
        }
    }

    const int n    = (sn < CAP) ? sn : CAP;
    const int n128 = (n + 127) & ~127;       // <= CAP
    for (int j = n + tid; j < n128; j += 256) dst[j] = 0;   // pads
    if (tid == 0) { g_cnt[k] = n128; g_base[k] = 1.0f - (float)(n128 - n); }
}

// ---------------- K_A: denominators (blocks 0..1023) + px-list build --------
// (blocks 1024..1087). The px-list half depends ONLY on rfs, so it rides in
// the same launch and overlaps with the denominator blocks.
// Denominators: exp(v-m)/(exp(-m)+sum exp(v-m)) == exp(v)/(1+sum exp(v));
// warp-per-(bc,k), branch-free thanks to x128 padding.
// Px lists: 4 threads per pixel (16 k each), shfl prefix, NO barriers.
__global__ __launch_bounds__(256) void denom_px(const float* __restrict__ u,
                                                const float* __restrict__ rfs) {
    const int tid = threadIdx.x;

    if (blockIdx.x < 1024) {
        const int bc   = blockIdx.x >> 3;
        const int kc   = blockIdx.x & 7;
        const int lane = tid & 31;
        const int k    = kc*8 + (tid >> 5);

        const int n128 = g_cnt[k];
        const int* __restrict__ pr = g_pk + k*CAP;
        const float* __restrict__ ub = u + bc*HWV;

        float s0 = 0.0f, s1 = 0.0f, s2 = 0.0f, s3 = 0.0f;
        for (int j = lane; j < n128; j += 128) {
            const int b0 = pr[j];
            const int b1 = pr[j + 32];
            const int b2 = pr[j + 64];
            const int b3 = pr[j + 96];
            s0 += ex2_fast(ub[b0 & 0xFFF] * __int_as_float(b0 & 0xFFFFF000));
            s1 += ex2_fast(ub[b1 & 0xFFF] * __int_as_float(b1 & 0xFFFFF000));
            s2 += ex2_fast(ub[b2 & 0xFFF] * __int_as_float(b2 & 0xFFFFF000));
            s3 += ex2_fast(ub[b3 & 0xFFF] * __int_as_float(b3 & 0xFFFFF000));
        }
        float sum = (s0 + s1) + (s2 + s3);
        #pragma unroll
        for (int o = 16; o > 0; o >>= 1) sum += __shfl_down_sync(0xffffffffu, sum, o);
        if (lane == 0) g_inv[bc*KK + k] = 1.0f / (g_base[k] + sum);
    } else {
        // px-list build: 64 blocks x 64 pixels; 4 threads per pixel.
        const float LOG2E = 1.4426950408889634f;
        const int q  = tid & 3;                  // k-quarter (16 k)
        const int pl = tid >> 2;                 // pixel within block
        const int ug = (blockIdx.x - 1024) * 16 + (pl >> 2);
        const int wn = pl & 3;                   // pixel within unit
        const int y  = 2*(ug >> 5) + (wn >> 1);
        const int x  = 2*(ug & 31) + (wn & 1);
        const int p  = y*WW + x;

        float rv[16];
        int cq = 0;
        #pragma unroll
        for (int i = 0; i < 16; i++) {
            rv[i] = rfs[(q*16 + i)*HWV + p];     // 16 independent LDGs
            cq += (rv[i] != 0.0f);
        }

        // exclusive prefix of cq over the 4-lane pixel group
        int off = 0;
        #pragma unroll
        for (int o = 1; o < 4; o++) {
            const int t = __shfl_up_sync(0xffffffffu, cq, o);
            if (q >= o) off += t;
        }
        // pixel total, then unit max over the 16-lane unit group
        int ct = cq;
        ct += __shfl_xor_sync(0xffffffffu, ct, 1);
        ct += __shfl_xor_sync(0xffffffffu, ct, 2);   // all 4 lanes: pixel total
        int cm = ct;
        cm = max(cm, __shfl_xor_sync(0xffffffffu, cm, 4));
        cm = max(cm, __shfl_xor_sync(0xffffffffu, cm, 8));
        const int cm4 = (cm + 3) & ~3;

        #pragma unroll
        for (int i = 0; i < 16; i++) {
            if (rv[i] != 0.0f) {
                const int k    = q*16 + i;
                const int bits = ((__float_as_int(rv[i]*LOG2E) + 0x40) & 0xFFFFFF80) | k;
                g_pxt[(off*NU + ug)*4 + wn] = bits;
                off++;
            }
        }
        if (q == 3) {                            // off == ct here; pad to cm4
            for (int j = ct; j < cm4; j++)
                g_pxt[(j*NU + ug)*4 + wn] = 64;  // null: rf=+0, k=64 -> 0
            if (wn == 0) g_uc[ug] = cm4;
        }
    }
}

// ---------------- K_B: per-unit numerators + max, direct store --------------
// Thread = one output unit: 4 register accumulators (its 2x2 pixels), one
// coalesced LDG.128 per list entry-row, unrolled x4 (16 entries in flight).
__global__ __launch_bounds__(256) void k_numer(const float* __restrict__ u,
                                               float* __restrict__ out) {
    __shared__ float inv_s[128];     // [64..127] = 0 for null entries

    const int bc  = blockIdx.x >> 2;
    const int seg = blockIdx.x & 3;
    const int tid = threadIdx.x;

    if (tid < 64)        inv_s[tid] = g_inv[bc*KK + tid];
    else if (tid < 128)  inv_s[tid] = 0.0f;
    __syncthreads();

    const int ug = seg*256 + tid;                // global unit
    const int gb = bc*HWV + 2*(ug >> 5)*WW + 2*(ug & 31);
    const float u0 = u[gb], u1 = u[gb + 1], u2 = u[gb + WW], u3 = u[gb + WW + 1];
    const int cn = g_uc[ug];                     // multiple of 4

    const int4* __restrict__ PT = (const int4*)g_pxt;
    float a0 = 0.0f, a1 = 0.0f, a2 = 0.0f, a3 = 0.0f;

    #define RFV(b) __int_as_float((b) & 0xFFFFFF80)
    for (int j = 0; j < cn; j += 4) {
        const int4 b0 = PT[(j + 0)*NU + ug];     // 4 independent LDG.128,
        const int4 b1 = PT[(j + 1)*NU + ug];     // perfectly lane-coalesced
        const int4 b2 = PT[(j + 2)*NU + ug];
        const int4 b3 = PT[(j + 3)*NU + ug];
        a0 += ex2_fast(u0 * RFV(b0.x)) * inv_s[b0.x & 127];
        a1 += ex2_fast(u1 * RFV(b0.y)) * inv_s[b0.y & 127];
        a2 += ex2_fast(u2 * RFV(b0.z)) * inv_s[b0.z & 127];
        a3 += ex2_fast(u3 * RFV(b0.w)) * inv_s[b0.w & 127];
        a0 += ex2_fast(u0 * RFV(b1.x)) * inv_s[b1.x & 127];
        a1 += ex2_fast(u1 * RFV(b1.y)) * inv_s[b1.y & 127];
        a2 += ex2_fast(u2 * RFV(b1.z)) * inv_s[b1.z & 127];
        a3 += ex2_fast(u3 * RFV(b1.w)) * inv_s[b1.w & 127];
        a0 += ex2_fast(u0 * RFV(b2.x)) * inv_s[b2.x & 127];
        a1 += ex2_fast(u1 * RFV(b2.y)) * inv_s[b2.y & 127];
        a2 += ex2_fast(u2 * RFV(b2.z)) * inv_s[b2.z & 127];
        a3 += ex2_fast(u3 * RFV(b2.w)) * inv_s[b2.w & 127];
        a0 += ex2_fast(u0 * RFV(b3.x)) * inv_s[b3.x & 127];
        a1 += ex2_fast(u1 * RFV(b3.y)) * inv_s[b3.y & 127];
        a2 += ex2_fast(u2 * RFV(b3.z)) * inv_s[b3.z & 127];
        a3 += ex2_fast(u3 * RFV(b3.w)) * inv_s[b3.w & 127];
    }
    #undef RFV

    const float best = fmaxf(fmaxf(fmaxf(a0, a1), fmaxf(a2, a3)), 0.0f);
    out[bc*NU + ug] = best;
}

// ---------------- launch -----------------------------------------------------
extern "C" void kernel_launch(void* const* d_in, const int* in_sizes, int n_in,
                              void* d_out, int out_size) {
    const float* u   = (const float*)d_in[0];   // (4,32,64,64)
    const float* rfs = (const float*)d_in[1];   // (64,64,64)
    float* out = (float*)d_out;                 // (4,32,32,32)

    prep_k  <<<64,        256>>>(rfs);
    denom_px<<<1024 + 64, 256>>>(u, rfs);
    k_numer <<<BCV*4,     256>>>(u, out);
}